// round 8
// baseline (speedup 1.0000x reference)
#include <cuda_runtime.h>

// ----------------------------------------------------------------------------
// MultiHeadSelfAttention: B=2, S=2048, D_MODEL=1024, H=16, depth=64, fp32.
// Round 7: all matmuls on tensor cores via 3xTF32 mma.sync.m16n8k8
// (hi/lo mantissa split -> fp32-equivalent accuracy, ~3x tensor ops).
// ----------------------------------------------------------------------------

#define D_MODEL   1024
#define NUM_HEADS 16
#define DEPTH     64
#define BATCH     2
#define SEQ       2048
#define M_TOK     (BATCH * SEQ)

__device__ float g_q[M_TOK * D_MODEL];
__device__ float g_k[M_TOK * D_MODEL];
__device__ float g_v[M_TOK * D_MODEL];
__device__ float g_attn[M_TOK * D_MODEL];

// ---------------------------- tf32 helpers ----------------------------------

__device__ __forceinline__ unsigned f2tf(float x) {
    unsigned r;
    asm("cvt.rna.tf32.f32 %0, %1;" : "=r"(r) : "f"(x));
    return r;
}
// x = tf32(hi) + tf32(lo) (lo captures mantissa bits 11..21; ll term dropped)
__device__ __forceinline__ void split_tf(float x, unsigned &hi, unsigned &lo) {
    hi = f2tf(x);
    lo = f2tf(x - __uint_as_float(hi));
}
// D += A(16x8,row) * B(8x8,col); A=4 regs, B=2 regs, C=4 f32.
__device__ __forceinline__ void mma8(float* c, const unsigned* a, const unsigned* b) {
    asm volatile(
        "mma.sync.aligned.m16n8k8.row.col.f32.tf32.tf32.f32 "
        "{%0,%1,%2,%3}, {%4,%5,%6,%7}, {%8,%9}, {%0,%1,%2,%3};"
        : "+f"(c[0]), "+f"(c[1]), "+f"(c[2]), "+f"(c[3])
        : "r"(a[0]), "r"(a[1]), "r"(a[2]), "r"(a[3]),
          "r"(b[0]), "r"(b[1]));
}

// ======================= GEMM: C = A @ W + bias =============================
// 128x128 block tile, k-tile 32, 8 warps in 2(m) x 4(n), warp tile 64x32.
// fp32 tiles in smem; hi/lo split in registers; 3 mma per (mf,nf,kstep).

#define GAS 36    // As row stride (32 + 4)
#define GBS 132   // Bs row stride (128 + 4)

__device__ __forceinline__ void gemm_tc_body(
    const float* __restrict__ A,
    const float* __restrict__ W,
    const float* __restrict__ bias,
    float* __restrict__ C,
    float* As, float* Bs)   // As[128][GAS], Bs[32][GBS]
{
    const int tid  = threadIdx.x;
    const int warp = tid >> 5;
    const int lane = tid & 31;
    const int g    = lane >> 2;       // 0..7
    const int tg   = lane & 3;        // 0..3
    const int wm   = warp >> 2;       // 0..1
    const int wn   = warp & 3;        // 0..3
    const int brow = blockIdx.y;
    const int bcol = blockIdx.x;

    float c[4][4][4];
    #pragma unroll
    for (int mf = 0; mf < 4; mf++)
        #pragma unroll
        for (int nf = 0; nf < 4; nf++)
            #pragma unroll
            for (int i = 0; i < 4; i++) c[mf][nf][i] = 0.0f;

    // Loaders (A: 128x32, B: 32x128; 4 float4 each per thread)
    const int arow = tid >> 3;          // 0..31  (+ i*32)
    const int acol = (tid & 7) << 2;    // 0..28
    const int brW  = tid >> 5;          // 0..7   (+ i*8)
    const int bcW  = (tid & 31) << 2;   // 0..124

    const float* Ag = A + (size_t)(brow * 128) * D_MODEL;
    const float* Wg = W + bcol * 128;

    float4 av[4], bv[4];
    #pragma unroll
    for (int i = 0; i < 4; i++) {
        av[i] = *(const float4*)(Ag + (size_t)(i * 32 + arow) * D_MODEL + acol);
        bv[i] = *(const float4*)(Wg + (size_t)(i * 8 + brW) * D_MODEL + bcW);
    }

    for (int kt = 0; kt < D_MODEL / 32; kt++) {
        #pragma unroll
        for (int i = 0; i < 4; i++) {
            *(float4*)&As[(i * 32 + arow) * GAS + acol] = av[i];
            *(float4*)&Bs[(i * 8 + brW) * GBS + bcW]    = bv[i];
        }
        __syncthreads();

        if (kt + 1 < D_MODEL / 32) {
            int k0 = (kt + 1) * 32;
            #pragma unroll
            for (int i = 0; i < 4; i++) {
                av[i] = *(const float4*)(Ag + (size_t)(i * 32 + arow) * D_MODEL + k0 + acol);
                bv[i] = *(const float4*)(Wg + (size_t)(k0 + i * 8 + brW) * D_MODEL + bcW);
            }
        }

        #pragma unroll
        for (int ks = 0; ks < 4; ks++) {
            const int kk = ks * 8;
            unsigned ah[4][4], al[4][4];
            #pragma unroll
            for (int mf = 0; mf < 4; mf++) {
                int r = wm * 64 + mf * 16 + g;
                split_tf(As[r * GAS + kk + tg],           ah[mf][0], al[mf][0]);
                split_tf(As[(r + 8) * GAS + kk + tg],     ah[mf][1], al[mf][1]);
                split_tf(As[r * GAS + kk + tg + 4],       ah[mf][2], al[mf][2]);
                split_tf(As[(r + 8) * GAS + kk + tg + 4], ah[mf][3], al[mf][3]);
            }
            unsigned bh[4][2], bl[4][2];
            #pragma unroll
            for (int nf = 0; nf < 4; nf++) {
                int cn = wn * 32 + nf * 8 + g;
                split_tf(Bs[(kk + tg) * GBS + cn],     bh[nf][0], bl[nf][0]);
                split_tf(Bs[(kk + tg + 4) * GBS + cn], bh[nf][1], bl[nf][1]);
            }
            #pragma unroll
            for (int mf = 0; mf < 4; mf++)
                #pragma unroll
                for (int nf = 0; nf < 4; nf++) {
                    mma8(c[mf][nf], ah[mf], bh[nf]);
                    mma8(c[mf][nf], al[mf], bh[nf]);
                    mma8(c[mf][nf], ah[mf], bl[nf]);
                }
        }
        __syncthreads();
    }

    // Epilogue: c0,c1 are adjacent cols -> float2 stores.
    #pragma unroll
    for (int mf = 0; mf < 4; mf++) {
        int row0 = brow * 128 + wm * 64 + mf * 16 + g;
        #pragma unroll
        for (int nf = 0; nf < 4; nf++) {
            int col = bcol * 128 + wn * 32 + nf * 8 + 2 * tg;
            float b0 = bias[col], b1 = bias[col + 1];
            float2 v0 = make_float2(c[mf][nf][0] + b0, c[mf][nf][1] + b1);
            float2 v1 = make_float2(c[mf][nf][2] + b0, c[mf][nf][3] + b1);
            *(float2*)(C + (size_t)row0 * D_MODEL + col)       = v0;
            *(float2*)(C + (size_t)(row0 + 8) * D_MODEL + col) = v1;
        }
    }
}

__global__ __launch_bounds__(256, 1)
void qkv_kernel(const float* __restrict__ X,
                const float* __restrict__ wq, const float* __restrict__ bq,
                const float* __restrict__ wk, const float* __restrict__ bk,
                const float* __restrict__ wv, const float* __restrict__ bv)
{
    __shared__ float As[128 * GAS];
    __shared__ float Bs[32 * GBS];
    const float* W; const float* bias; float* C;
    if (blockIdx.z == 0)      { W = wq; bias = bq; C = g_q; }
    else if (blockIdx.z == 1) { W = wk; bias = bk; C = g_k; }
    else                      { W = wv; bias = bv; C = g_v; }
    gemm_tc_body(X, W, bias, C, As, Bs);
}

__global__ __launch_bounds__(256, 1)
void out_proj_kernel(const float* __restrict__ wo,
                     const float* __restrict__ bo,
                     float* __restrict__ out)
{
    __shared__ float As[128 * GAS];
    __shared__ float Bs[32 * GBS];
    gemm_tc_body(g_attn, wo, bo, out, As, Bs);
}

// ============================ Flash attention ===============================
// BR=128 q rows / block, BC=64 kv per tile, 8 warps, warp owns 16 full rows
// (softmax warp-local). Q frags (hi/lo tf32) in registers across all kv tiles.
// S and PV both 3xTF32. P round-trips through smem fp32 (warp-private rows).

#define KS_S 68   // Ksm row stride
#define VS_S 72   // Vsm row stride (64+8: keeps b-frag banks distinct)
#define PS_S 68   // Psm row stride

#define FLASH_SMEM ((64 * KS_S + 64 * VS_S + 128 * PS_S) * 4)  // 70656 B

__global__ __launch_bounds__(256, 1)
void flash_kernel()
{
    extern __shared__ float fsm[];
    float* Ksm = fsm;                         // [64][KS_S]
    float* Vsm = fsm + 64 * KS_S;             // [64][VS_S]
    float* Psm = fsm + 64 * KS_S + 64 * VS_S; // [128][PS_S], also Q staging

    const int tid  = threadIdx.x;
    const int warp = tid >> 5;
    const int lane = tid & 31;
    const int g    = lane >> 2;
    const int tg   = lane & 3;
    const int wbase = warp * 16;          // warp's 16 q rows within tile
    const int qt   = blockIdx.x;          // 0..15 (128 rows each)
    const int bh   = blockIdx.y;          // 0..31
    const int b    = bh >> 4;
    const int h    = bh & 15;

    const size_t base = (size_t)b * SEQ * D_MODEL + (size_t)h * DEPTH;
    const float* Qg = g_q    + base;
    const float* Kg = g_k    + base;
    const float* Vg = g_v    + base;
    float*       Og = g_attn + base;

    // ---- Stage Q (scaled) into Psm, then lift into register fragments ----
    #pragma unroll
    for (int i = 0; i < 8; i++) {
        int idx = i * 256 + tid;
        int r   = idx >> 4;                // 0..127
        int c4  = (idx & 15) << 2;         // 0..60
        float4 v = *(const float4*)(Qg + (size_t)(qt * 128 + r) * D_MODEL + c4);
        float* dst = &Psm[r * PS_S + c4];
        dst[0] = v.x * 0.125f; dst[1] = v.y * 0.125f;
        dst[2] = v.z * 0.125f; dst[3] = v.w * 0.125f;
    }
    __syncthreads();

    unsigned qhi[8][4], qlo[8][4];
    #pragma unroll
    for (int kf = 0; kf < 8; kf++) {
        int d0 = kf * 8;
        split_tf(Psm[(wbase + g) * PS_S + d0 + tg],         qhi[kf][0], qlo[kf][0]);
        split_tf(Psm[(wbase + g + 8) * PS_S + d0 + tg],     qhi[kf][1], qlo[kf][1]);
        split_tf(Psm[(wbase + g) * PS_S + d0 + tg + 4],     qhi[kf][2], qlo[kf][2]);
        split_tf(Psm[(wbase + g + 8) * PS_S + d0 + tg + 4], qhi[kf][3], qlo[kf][3]);
    }

    float o[8][4];
    #pragma unroll
    for (int nf = 0; nf < 8; nf++)
        #pragma unroll
        for (int i = 0; i < 4; i++) o[nf][i] = 0.0f;
    float m0 = -1e30f, m1 = -1e30f, l0 = 0.0f, l1 = 0.0f;

    for (int kt = 0; kt < SEQ / 64; kt++) {
        __syncthreads();   // prev iter's K/V reads complete (also covers Q stage)

        // Load K,V tiles (64x64 each; 4 float4 per thread per tensor).
        #pragma unroll
        for (int i = 0; i < 4; i++) {
            int idx = i * 256 + tid;
            int r   = idx >> 4;
            int c4  = (idx & 15) << 2;
            *(float4*)&Ksm[r * KS_S + c4] =
                *(const float4*)(Kg + (size_t)(kt * 64 + r) * D_MODEL + c4);
            *(float4*)&Vsm[r * VS_S + c4] =
                *(const float4*)(Vg + (size_t)(kt * 64 + r) * D_MODEL + c4);
        }
        __syncthreads();

        // ---- S = Qscaled @ K^T  (16 rows x 64 cols per warp) ----
        float s[8][4];
        #pragma unroll
        for (int nf = 0; nf < 8; nf++)
            #pragma unroll
            for (int i = 0; i < 4; i++) s[nf][i] = 0.0f;

        #pragma unroll
        for (int ks = 0; ks < 8; ks++) {
            int d0 = ks * 8;
            #pragma unroll
            for (int nf = 0; nf < 8; nf++) {
                int j = nf * 8 + g;
                unsigned bh2[2], bl2[2];
                split_tf(Ksm[j * KS_S + d0 + tg],     bh2[0], bl2[0]);
                split_tf(Ksm[j * KS_S + d0 + tg + 4], bh2[1], bl2[1]);
                mma8(s[nf], qhi[ks], bh2);
                mma8(s[nf], qlo[ks], bh2);
                mma8(s[nf], qhi[ks], bl2);
            }
        }

        // ---- online softmax (rows g and g+8 of this warp's 16) ----
        float mx0 = -1e30f, mx1 = -1e30f;
        #pragma unroll
        for (int nf = 0; nf < 8; nf++) {
            mx0 = fmaxf(mx0, fmaxf(s[nf][0], s[nf][1]));
            mx1 = fmaxf(mx1, fmaxf(s[nf][2], s[nf][3]));
        }
        mx0 = fmaxf(mx0, __shfl_xor_sync(0xffffffffu, mx0, 1));
        mx0 = fmaxf(mx0, __shfl_xor_sync(0xffffffffu, mx0, 2));
        mx1 = fmaxf(mx1, __shfl_xor_sync(0xffffffffu, mx1, 1));
        mx1 = fmaxf(mx1, __shfl_xor_sync(0xffffffffu, mx1, 2));

        float mn0 = fmaxf(m0, mx0), mn1 = fmaxf(m1, mx1);
        float a0 = __expf(m0 - mn0), a1 = __expf(m1 - mn1);
        m0 = mn0; m1 = mn1;

        float sum0 = 0.0f, sum1 = 0.0f;
        #pragma unroll
        for (int nf = 0; nf < 8; nf++) {
            s[nf][0] = __expf(s[nf][0] - mn0); sum0 += s[nf][0];
            s[nf][1] = __expf(s[nf][1] - mn0); sum0 += s[nf][1];
            s[nf][2] = __expf(s[nf][2] - mn1); sum1 += s[nf][2];
            s[nf][3] = __expf(s[nf][3] - mn1); sum1 += s[nf][3];
        }
        sum0 += __shfl_xor_sync(0xffffffffu, sum0, 1);
        sum0 += __shfl_xor_sync(0xffffffffu, sum0, 2);
        sum1 += __shfl_xor_sync(0xffffffffu, sum1, 1);
        sum1 += __shfl_xor_sync(0xffffffffu, sum1, 2);
        l0 = l0 * a0 + sum0;
        l1 = l1 * a1 + sum1;

        #pragma unroll
        for (int nf = 0; nf < 8; nf++) {
            o[nf][0] *= a0; o[nf][1] *= a0;
            o[nf][2] *= a1; o[nf][3] *= a1;
        }

        // ---- write P to smem (warp-private rows), then PV ----
        #pragma unroll
        for (int nf = 0; nf < 8; nf++) {
            int col = nf * 8 + 2 * tg;
            *(float2*)&Psm[(wbase + g) * PS_S + col]     = make_float2(s[nf][0], s[nf][1]);
            *(float2*)&Psm[(wbase + g + 8) * PS_S + col] = make_float2(s[nf][2], s[nf][3]);
        }
        __syncwarp();

        #pragma unroll
        for (int ks = 0; ks < 8; ks++) {
            int j0 = ks * 8;
            unsigned ph[4], pl[4];
            split_tf(Psm[(wbase + g) * PS_S + j0 + tg],         ph[0], pl[0]);
            split_tf(Psm[(wbase + g + 8) * PS_S + j0 + tg],     ph[1], pl[1]);
            split_tf(Psm[(wbase + g) * PS_S + j0 + tg + 4],     ph[2], pl[2]);
            split_tf(Psm[(wbase + g + 8) * PS_S + j0 + tg + 4], ph[3], pl[3]);
            #pragma unroll
            for (int nf = 0; nf < 8; nf++) {
                int d = nf * 8 + g;
                unsigned vh[2], vl[2];
                split_tf(Vsm[(j0 + tg) * VS_S + d],     vh[0], vl[0]);
                split_tf(Vsm[(j0 + tg + 4) * VS_S + d], vh[1], vl[1]);
                mma8(o[nf], ph, vh);
                mma8(o[nf], pl, vh);
                mma8(o[nf], ph, vl);
            }
        }
        __syncwarp();
    }

    // ---- normalize + write ----
    float inv0 = 1.0f / l0, inv1 = 1.0f / l1;
    int row0 = qt * 128 + wbase + g;
    #pragma unroll
    for (int nf = 0; nf < 8; nf++) {
        int col = nf * 8 + 2 * tg;
        *(float2*)(Og + (size_t)row0 * D_MODEL + col) =
            make_float2(o[nf][0] * inv0, o[nf][1] * inv0);
        *(float2*)(Og + (size_t)(row0 + 8) * D_MODEL + col) =
            make_float2(o[nf][2] * inv1, o[nf][3] * inv1);
    }
}

// ============================== launch ======================================

extern "C" void kernel_launch(void* const* d_in, const int* in_sizes, int n_in,
                              void* d_out, int out_size)
{
    const float* X  = (const float*)d_in[0];
    const float* wq = (const float*)d_in[1];
    const float* bq = (const float*)d_in[2];
    const float* wk = (const float*)d_in[3];
    const float* bk = (const float*)d_in[4];
    const float* wv = (const float*)d_in[5];
    const float* bv = (const float*)d_in[6];
    const float* wo = (const float*)d_in[7];
    const float* bo = (const float*)d_in[8];
    float* out = (float*)d_out;
    (void)in_sizes; (void)n_in; (void)out_size;

    cudaFuncSetAttribute(flash_kernel,
                         cudaFuncAttributeMaxDynamicSharedMemorySize,
                         FLASH_SMEM);

    dim3 gproj(D_MODEL / 128, M_TOK / 128, 3);   // 8 x 32 x 3
    qkv_kernel<<<gproj, 256>>>(X, wq, bq, wk, bk, wv, bv);

    dim3 gflash(SEQ / 128, BATCH * NUM_HEADS);   // 16 x 32
    flash_kernel<<<gflash, 256, FLASH_SMEM>>>();

    dim3 gout(D_MODEL / 128, M_TOK / 128);       // 8 x 32
    out_proj_kernel<<<gout, 256>>>(wo, bo, out);
}

// round 12
// speedup vs baseline: 2.3596x; 2.3596x over previous
#include <cuda_runtime.h>
#include <cuda_fp16.h>

// ----------------------------------------------------------------------------
// MultiHeadSelfAttention: B=2, S=2048, D_MODEL=1024, H=16, depth=64, fp32.
// Round 8: 3-term fp16 split on m16n8k16 HMMA (fp32 accum).
//   x = h + l (two fp16) => x*y ~ hh + hl + lh  (ll dropped, ~2^-22 rel)
// Tiles pre-split into f16 hi/lo smem in MMA fragment-pair layout.
// ----------------------------------------------------------------------------

#define D_MODEL   1024
#define NUM_HEADS 16
#define DEPTH     64
#define BATCH     2
#define SEQ       2048
#define M_TOK     (BATCH * SEQ)

typedef unsigned u32;

__device__ float g_q[M_TOK * D_MODEL];
__device__ float g_k[M_TOK * D_MODEL];
__device__ float g_v[M_TOK * D_MODEL];
__device__ float g_attn[M_TOK * D_MODEL];

// ---------------------------- helpers ---------------------------------------

// (x,y) -> packed f16x2 hi and f16x2 lo residual
__device__ __forceinline__ void split2(float x, float y, u32 &h, u32 &l) {
    __half2 hh = __floats2half2_rn(x, y);
    float2 hf = __half22float2(hh);
    __half2 ll = __floats2half2_rn(x - hf.x, y - hf.y);
    h = *reinterpret_cast<u32*>(&hh);
    l = *reinterpret_cast<u32*>(&ll);
}

// D(16x8 f32) += A(16x16 f16, row) * B(16x8 f16, col)
__device__ __forceinline__ void mma16(float* c, const u32* a, const u32* b) {
    asm volatile(
        "mma.sync.aligned.m16n8k16.row.col.f32.f16.f16.f32 "
        "{%0,%1,%2,%3}, {%4,%5,%6,%7}, {%8,%9}, {%0,%1,%2,%3};"
        : "+f"(c[0]), "+f"(c[1]), "+f"(c[2]), "+f"(c[3])
        : "r"(a[0]), "r"(a[1]), "r"(a[2]), "r"(a[3]),
          "r"(b[0]), "r"(b[1]));
}

__device__ __forceinline__ u32 prmt(u32 a, u32 b, u32 sel) {
    u32 r; asm("prmt.b32 %0, %1, %2, %3;" : "=r"(r) : "r"(a), "r"(b), "r"(sel));
    return r;
}

// ======================= GEMM: C = A @ W + bias =============================
// 128x128 block tile, ktile 32, 8 warps (2m x 4n), warp tile 64x32.
// Smem: Ah/Al u32[r][kpair] (pairs along k), Bh/Bl u32[kpair][n] (k-pairs
// packed at store via shfl(16)+prmt so the B fragment is one LDS.32).

#define AS 20    // Ah/Al row stride in u32 (16 kpairs + 4 pad)
#define BS 136   // Bh/Bl row stride in u32 (128 n + 8 pad)

__device__ __forceinline__ void gemm_body(
    const float* __restrict__ A,
    const float* __restrict__ W,
    const float* __restrict__ bias,
    float* __restrict__ C,
    u32* Ah, u32* Al, u32* Bh, u32* Bl)
{
    const int tid  = threadIdx.x;
    const int warp = tid >> 5;
    const int lane = tid & 31;
    const int g    = lane >> 2;
    const int tg   = lane & 3;
    const int wm   = warp >> 2;
    const int wn   = warp & 3;
    const int brow = blockIdx.y;
    const int bcol = blockIdx.x;

    float c[4][4][4];
    #pragma unroll
    for (int mf = 0; mf < 4; mf++)
        #pragma unroll
        for (int nf = 0; nf < 4; nf++)
            #pragma unroll
            for (int i = 0; i < 4; i++) c[mf][nf][i] = 0.0f;

    const int arow  = tid >> 3;          // 0..31 (+32i)
    const int acol  = (tid & 7) << 2;    // 0..28
    const int bln   = lane & 15;
    const int bhalf = lane >> 4;         // 0: even k row, 1: odd

    const float* Ag = A + (size_t)(brow * 128) * D_MODEL;
    const float* Wg = W + bcol * 128;

    float4 av[4], bv[2][2];
    #pragma unroll
    for (int i = 0; i < 4; i++)
        av[i] = *(const float4*)(Ag + (size_t)(i * 32 + arow) * D_MODEL + acol);
    #pragma unroll
    for (int i = 0; i < 2; i++) {
        int krow = 2 * (warp + 8 * i) + bhalf;
        #pragma unroll
        for (int j = 0; j < 2; j++)
            bv[i][j] = *(const float4*)(Wg + (size_t)krow * D_MODEL + 4 * bln + 64 * j);
    }

    for (int kt = 0; kt < D_MODEL / 32; kt++) {
        // ---- store tiles (split to f16 hi/lo) ----
        #pragma unroll
        for (int i = 0; i < 4; i++) {
            int r = i * 32 + arow;
            u32 h0, l0, h1, l1;
            split2(av[i].x, av[i].y, h0, l0);
            split2(av[i].z, av[i].w, h1, l1);
            *(uint2*)&Ah[r * AS + (acol >> 1)] = make_uint2(h0, h1);
            *(uint2*)&Al[r * AS + (acol >> 1)] = make_uint2(l0, l1);
        }
        #pragma unroll
        for (int i = 0; i < 2; i++) {
            int kp = warp + 8 * i;
            #pragma unroll
            for (int j = 0; j < 2; j++) {
                u32 h2a, l2a, h2b, l2b;
                split2(bv[i][j].x, bv[i][j].y, h2a, l2a);
                split2(bv[i][j].z, bv[i][j].w, h2b, l2b);
                u32 ph2a = __shfl_xor_sync(0xffffffffu, h2a, 16);
                u32 ph2b = __shfl_xor_sync(0xffffffffu, h2b, 16);
                u32 pl2a = __shfl_xor_sync(0xffffffffu, l2a, 16);
                u32 pl2b = __shfl_xor_sync(0xffffffffu, l2b, 16);
                int col = 4 * bln + 64 * j;
                if (bhalf == 0) {   // own = even k (low half of pair)
                    uint4 o = make_uint4(prmt(h2a, ph2a, 0x5410),
                                         prmt(h2a, ph2a, 0x7632),
                                         prmt(h2b, ph2b, 0x5410),
                                         prmt(h2b, ph2b, 0x7632));
                    *(uint4*)&Bh[kp * BS + col] = o;
                } else {            // own = odd k (high half); partner = even
                    uint4 o = make_uint4(prmt(pl2a, l2a, 0x5410),
                                         prmt(pl2a, l2a, 0x7632),
                                         prmt(pl2b, l2b, 0x5410),
                                         prmt(pl2b, l2b, 0x7632));
                    *(uint4*)&Bl[kp * BS + col] = o;
                }
            }
        }
        __syncthreads();

        // ---- prefetch next ktile ----
        if (kt + 1 < D_MODEL / 32) {
            int k0 = (kt + 1) * 32;
            #pragma unroll
            for (int i = 0; i < 4; i++)
                av[i] = *(const float4*)(Ag + (size_t)(i * 32 + arow) * D_MODEL + k0 + acol);
            #pragma unroll
            for (int i = 0; i < 2; i++) {
                int krow = k0 + 2 * (warp + 8 * i) + bhalf;
                #pragma unroll
                for (int j = 0; j < 2; j++)
                    bv[i][j] = *(const float4*)(Wg + (size_t)krow * D_MODEL + 4 * bln + 64 * j);
            }
        }

        // ---- MMA: 2 k-steps of 16 ----
        #pragma unroll
        for (int ks = 0; ks < 2; ks++) {
            u32 ah[4][4], al[4][4];
            #pragma unroll
            for (int mf = 0; mf < 4; mf++) {
                int r0 = (wm * 64 + mf * 16 + g) * AS;
                int r1 = r0 + 8 * AS;
                int kb = 8 * ks + tg;
                ah[mf][0] = Ah[r0 + kb];     ah[mf][1] = Ah[r1 + kb];
                ah[mf][2] = Ah[r0 + kb + 4]; ah[mf][3] = Ah[r1 + kb + 4];
                al[mf][0] = Al[r0 + kb];     al[mf][1] = Al[r1 + kb];
                al[mf][2] = Al[r0 + kb + 4]; al[mf][3] = Al[r1 + kb + 4];
            }
            u32 bh[4][2], bl[4][2];
            #pragma unroll
            for (int nf = 0; nf < 4; nf++) {
                int cn = wn * 32 + nf * 8 + g;
                bh[nf][0] = Bh[(8 * ks + tg) * BS + cn];
                bh[nf][1] = Bh[(8 * ks + tg + 4) * BS + cn];
                bl[nf][0] = Bl[(8 * ks + tg) * BS + cn];
                bl[nf][1] = Bl[(8 * ks + tg + 4) * BS + cn];
            }
            #pragma unroll
            for (int mf = 0; mf < 4; mf++)
                #pragma unroll
                for (int nf = 0; nf < 4; nf++) {
                    mma16(c[mf][nf], ah[mf], bh[nf]);
                    mma16(c[mf][nf], al[mf], bh[nf]);
                    mma16(c[mf][nf], ah[mf], bl[nf]);
                }
        }
        __syncthreads();
    }

    #pragma unroll
    for (int mf = 0; mf < 4; mf++) {
        int row0 = brow * 128 + wm * 64 + mf * 16 + g;
        #pragma unroll
        for (int nf = 0; nf < 4; nf++) {
            int col = bcol * 128 + wn * 32 + nf * 8 + 2 * tg;
            float b0 = bias[col], b1 = bias[col + 1];
            *(float2*)(C + (size_t)row0 * D_MODEL + col) =
                make_float2(c[mf][nf][0] + b0, c[mf][nf][1] + b1);
            *(float2*)(C + (size_t)(row0 + 8) * D_MODEL + col) =
                make_float2(c[mf][nf][2] + b0, c[mf][nf][3] + b1);
        }
    }
}

__global__ __launch_bounds__(256)
void qkv_kernel(const float* __restrict__ X,
                const float* __restrict__ wq, const float* __restrict__ bq,
                const float* __restrict__ wk, const float* __restrict__ bk,
                const float* __restrict__ wv, const float* __restrict__ bv)
{
    __shared__ __align__(16) u32 Ah[128 * AS];
    __shared__ __align__(16) u32 Al[128 * AS];
    __shared__ __align__(16) u32 Bh[16 * BS];
    __shared__ __align__(16) u32 Bl[16 * BS];
    const float* W; const float* bias; float* C;
    if (blockIdx.z == 0)      { W = wq; bias = bq; C = g_q; }
    else if (blockIdx.z == 1) { W = wk; bias = bk; C = g_k; }
    else                      { W = wv; bias = bv; C = g_v; }
    gemm_body(X, W, bias, C, Ah, Al, Bh, Bl);
}

__global__ __launch_bounds__(256)
void out_proj_kernel(const float* __restrict__ wo,
                     const float* __restrict__ bo,
                     float* __restrict__ out)
{
    __shared__ __align__(16) u32 Ah[128 * AS];
    __shared__ __align__(16) u32 Al[128 * AS];
    __shared__ __align__(16) u32 Bh[16 * BS];
    __shared__ __align__(16) u32 Bl[16 * BS];
    gemm_body(g_attn, wo, bo, out, Ah, Al, Bh, Bl);
}

// ============================ Flash attention ===============================
// 128 q rows / block, 64 kv per tile, 8 warps; warp owns 16 full rows.
// Q hi/lo frags in registers for the whole loop; K split to [j][dpair] smem;
// V split to [kvpair][d] smem (kv-pairing via shfl(16)+prmt at store).
// P converts register->register into PV A-fragments (no smem round trip).

#define KSS 36   // Kh/Kl row stride in u32 (32 dpairs + 4 pad)
#define VSS 72   // Vh/Vl row stride in u32 (64 d + 8 pad)

__global__ __launch_bounds__(256)
void flash_kernel()
{
    __shared__ __align__(16) u32 Kh[64 * KSS];
    __shared__ __align__(16) u32 Kl[64 * KSS];
    __shared__ __align__(16) u32 Vh[32 * VSS];
    __shared__ __align__(16) u32 Vl[32 * VSS];

    const int tid   = threadIdx.x;
    const int warp  = tid >> 5;
    const int lane  = tid & 31;
    const int g     = lane >> 2;
    const int tg    = lane & 3;
    const int wbase = warp * 16;
    const int qt    = blockIdx.x;      // 0..15
    const int bh_   = blockIdx.y;      // 0..31
    const int b     = bh_ >> 4;
    const int h     = bh_ & 15;

    const size_t base = (size_t)b * SEQ * D_MODEL + (size_t)h * DEPTH;
    const float* Qg = g_q    + base;
    const float* Kg = g_k    + base;
    const float* Vg = g_v    + base;
    float*       Og = g_attn + base;

    // ---- Q fragments (scaled by 1/8), hi/lo, register resident ----
    u32 qh[4][4], ql[4][4];
    #pragma unroll
    for (int ks = 0; ks < 4; ks++) {
        int r0 = qt * 128 + wbase + g;
        int col = 16 * ks + 2 * tg;
        #pragma unroll
        for (int p = 0; p < 4; p++) {       // p: {r0,c}, {r0+8,c}, {r0,c+8}, {r0+8,c+8}
            int rr = r0 + (p & 1) * 8;
            int cc = col + (p >> 1) * 8;
            float2 v = *(const float2*)(Qg + (size_t)rr * D_MODEL + cc);
            split2(v.x * 0.125f, v.y * 0.125f, qh[ks][p], ql[ks][p]);
        }
    }

    float o[8][4];
    #pragma unroll
    for (int nf = 0; nf < 8; nf++)
        #pragma unroll
        for (int i = 0; i < 4; i++) o[nf][i] = 0.0f;
    float m0 = -1e30f, m1 = -1e30f, l0 = 0.0f, l1 = 0.0f;

    for (int kt = 0; kt < SEQ / 64; kt++) {
        __syncthreads();

        // ---- load + split K and V ----
        #pragma unroll
        for (int i = 0; i < 4; i++) {
            int idx = i * 256 + tid;
            int r   = idx >> 4;                // kv row 0..63
            int c4  = (idx & 15) << 2;         // d 0..60
            float4 kv4 = *(const float4*)(Kg + (size_t)(kt * 64 + r) * D_MODEL + c4);
            u32 kh0, kl0, kh1, kl1;
            split2(kv4.x, kv4.y, kh0, kl0);
            split2(kv4.z, kv4.w, kh1, kl1);
            *(uint2*)&Kh[r * KSS + (c4 >> 1)] = make_uint2(kh0, kh1);
            *(uint2*)&Kl[r * KSS + (c4 >> 1)] = make_uint2(kl0, kl1);

            float4 vv4 = *(const float4*)(Vg + (size_t)(kt * 64 + r) * D_MODEL + c4);
            u32 h2a, l2a, h2b, l2b;
            split2(vv4.x, vv4.y, h2a, l2a);
            split2(vv4.z, vv4.w, h2b, l2b);
            u32 ph2a = __shfl_xor_sync(0xffffffffu, h2a, 16);
            u32 ph2b = __shfl_xor_sync(0xffffffffu, h2b, 16);
            u32 pl2a = __shfl_xor_sync(0xffffffffu, l2a, 16);
            u32 pl2b = __shfl_xor_sync(0xffffffffu, l2b, 16);
            int rp = r >> 1;
            if ((lane >> 4) == 0) {            // own = even kv row
                uint4 ov = make_uint4(prmt(h2a, ph2a, 0x5410),
                                      prmt(h2a, ph2a, 0x7632),
                                      prmt(h2b, ph2b, 0x5410),
                                      prmt(h2b, ph2b, 0x7632));
                *(uint4*)&Vh[rp * VSS + c4] = ov;
            } else {                           // own = odd kv row
                uint4 ov = make_uint4(prmt(pl2a, l2a, 0x5410),
                                      prmt(pl2a, l2a, 0x7632),
                                      prmt(pl2b, l2b, 0x5410),
                                      prmt(pl2b, l2b, 0x7632));
                *(uint4*)&Vl[rp * VSS + c4] = ov;
            }
        }
        __syncthreads();

        // ---- S = Qs @ K^T : warp's 16 rows x 64 cols ----
        float s[8][4];
        #pragma unroll
        for (int nf = 0; nf < 8; nf++)
            #pragma unroll
            for (int i = 0; i < 4; i++) s[nf][i] = 0.0f;

        #pragma unroll
        for (int ks = 0; ks < 4; ks++) {
            #pragma unroll
            for (int nf = 0; nf < 8; nf++) {
                int j = nf * 8 + g;
                u32 kh2[2], kl2[2];
                kh2[0] = Kh[j * KSS + 8 * ks + tg];
                kh2[1] = Kh[j * KSS + 8 * ks + tg + 4];
                kl2[0] = Kl[j * KSS + 8 * ks + tg];
                kl2[1] = Kl[j * KSS + 8 * ks + tg + 4];
                mma16(s[nf], qh[ks], kh2);
                mma16(s[nf], ql[ks], kh2);
                mma16(s[nf], qh[ks], kl2);
            }
        }

        // ---- online softmax (rows g and g+8) ----
        float mx0 = -1e30f, mx1 = -1e30f;
        #pragma unroll
        for (int nf = 0; nf < 8; nf++) {
            mx0 = fmaxf(mx0, fmaxf(s[nf][0], s[nf][1]));
            mx1 = fmaxf(mx1, fmaxf(s[nf][2], s[nf][3]));
        }
        mx0 = fmaxf(mx0, __shfl_xor_sync(0xffffffffu, mx0, 1));
        mx0 = fmaxf(mx0, __shfl_xor_sync(0xffffffffu, mx0, 2));
        mx1 = fmaxf(mx1, __shfl_xor_sync(0xffffffffu, mx1, 1));
        mx1 = fmaxf(mx1, __shfl_xor_sync(0xffffffffu, mx1, 2));

        float mn0 = fmaxf(m0, mx0), mn1 = fmaxf(m1, mx1);
        float a0 = __expf(m0 - mn0), a1 = __expf(m1 - mn1);
        m0 = mn0; m1 = mn1;

        float sum0 = 0.0f, sum1 = 0.0f;
        #pragma unroll
        for (int nf = 0; nf < 8; nf++) {
            s[nf][0] = __expf(s[nf][0] - mn0); sum0 += s[nf][0];
            s[nf][1] = __expf(s[nf][1] - mn0); sum0 += s[nf][1];
            s[nf][2] = __expf(s[nf][2] - mn1); sum1 += s[nf][2];
            s[nf][3] = __expf(s[nf][3] - mn1); sum1 += s[nf][3];
        }
        sum0 += __shfl_xor_sync(0xffffffffu, sum0, 1);
        sum0 += __shfl_xor_sync(0xffffffffu, sum0, 2);
        sum1 += __shfl_xor_sync(0xffffffffu, sum1, 1);
        sum1 += __shfl_xor_sync(0xffffffffu, sum1, 2);
        l0 = l0 * a0 + sum0;
        l1 = l1 * a1 + sum1;

        #pragma unroll
        for (int nf = 0; nf < 8; nf++) {
            o[nf][0] *= a0; o[nf][1] *= a0;
            o[nf][2] *= a1; o[nf][3] *= a1;
        }

        // ---- PV: P frags built directly from s registers ----
        #pragma unroll
        for (int ks = 0; ks < 4; ks++) {
            u32 ph[4], pl[4];
            split2(s[2 * ks][0],     s[2 * ks][1],     ph[0], pl[0]);
            split2(s[2 * ks][2],     s[2 * ks][3],     ph[1], pl[1]);
            split2(s[2 * ks + 1][0], s[2 * ks + 1][1], ph[2], pl[2]);
            split2(s[2 * ks + 1][2], s[2 * ks + 1][3], ph[3], pl[3]);
            #pragma unroll
            for (int nf = 0; nf < 8; nf++) {
                int d = nf * 8 + g;
                u32 vh2[2], vl2[2];
                vh2[0] = Vh[(8 * ks + tg) * VSS + d];
                vh2[1] = Vh[(8 * ks + tg + 4) * VSS + d];
                vl2[0] = Vl[(8 * ks + tg) * VSS + d];
                vl2[1] = Vl[(8 * ks + tg + 4) * VSS + d];
                mma16(o[nf], ph, vh2);
                mma16(o[nf], pl, vh2);
                mma16(o[nf], ph, vl2);
            }
        }
    }

    // ---- normalize + write ----
    float inv0 = 1.0f / l0, inv1 = 1.0f / l1;
    int row0 = qt * 128 + wbase + g;
    #pragma unroll
    for (int nf = 0; nf < 8; nf++) {
        int col = nf * 8 + 2 * tg;
        *(float2*)(Og + (size_t)row0 * D_MODEL + col) =
            make_float2(o[nf][0] * inv0, o[nf][1] * inv0);
        *(float2*)(Og + (size_t)(row0 + 8) * D_MODEL + col) =
            make_float2(o[nf][2] * inv1, o[nf][3] * inv1);
    }
}

// ============================== launch ======================================

extern "C" void kernel_launch(void* const* d_in, const int* in_sizes, int n_in,
                              void* d_out, int out_size)
{
    const float* X  = (const float*)d_in[0];
    const float* wq = (const float*)d_in[1];
    const float* bq = (const float*)d_in[2];
    const float* wk = (const float*)d_in[3];
    const float* bk = (const float*)d_in[4];
    const float* wv = (const float*)d_in[5];
    const float* bv = (const float*)d_in[6];
    const float* wo = (const float*)d_in[7];
    const float* bo = (const float*)d_in[8];
    float* out = (float*)d_out;
    (void)in_sizes; (void)n_in; (void)out_size;

    dim3 gproj(D_MODEL / 128, M_TOK / 128, 3);   // 8 x 32 x 3
    qkv_kernel<<<gproj, 256>>>(X, wq, bq, wk, bk, wv, bv);

    dim3 gflash(SEQ / 128, BATCH * NUM_HEADS);   // 16 x 32
    flash_kernel<<<gflash, 256>>>();

    dim3 gout(D_MODEL / 128, M_TOK / 128);       // 8 x 32
    out_proj_kernel<<<gout, 256>>>(wo, bo, out);
}

// round 13
// speedup vs baseline: 2.7228x; 1.1539x over previous
#include <cuda_runtime.h>
#include <cuda_fp16.h>

// ----------------------------------------------------------------------------
// MultiHeadSelfAttention: B=2, S=2048, D_MODEL=1024, H=16, depth=64, fp32.
// Round 12: pre-split f16 hi/lo storage for all intermediates + double-buffered
// smem pipelines (1 sync per k-tile). Numerics identical to R8 3-term split.
// ----------------------------------------------------------------------------

#define D_MODEL   1024
#define NUM_HEADS 16
#define DEPTH     64
#define BATCH     2
#define SEQ       2048
#define M_TOK     (BATCH * SEQ)
#define U         (D_MODEL / 2)      // u32 (f16x2 pair) pitch per token row

typedef unsigned u32;

// Split intermediates: [token][d/2] u32 = f16x2 pair (d, d+1); hi and lo arrays.
__device__ __align__(16) u32 g_qh[M_TOK * U];
__device__ __align__(16) u32 g_ql[M_TOK * U];
__device__ __align__(16) u32 g_kh[M_TOK * U];
__device__ __align__(16) u32 g_kl[M_TOK * U];
__device__ __align__(16) u32 g_vh[M_TOK * U];
__device__ __align__(16) u32 g_vl[M_TOK * U];
__device__ __align__(16) u32 g_ah[M_TOK * U];
__device__ __align__(16) u32 g_al[M_TOK * U];

// ---------------------------- helpers ---------------------------------------

__device__ __forceinline__ void split2(float x, float y, u32 &h, u32 &l) {
    __half2 hh = __floats2half2_rn(x, y);
    float2 hf = __half22float2(hh);
    __half2 ll = __floats2half2_rn(x - hf.x, y - hf.y);
    h = *reinterpret_cast<u32*>(&hh);
    l = *reinterpret_cast<u32*>(&ll);
}

__device__ __forceinline__ void mma16(float* c, const u32* a, const u32* b) {
    asm volatile(
        "mma.sync.aligned.m16n8k16.row.col.f32.f16.f16.f32 "
        "{%0,%1,%2,%3}, {%4,%5,%6,%7}, {%8,%9}, {%0,%1,%2,%3};"
        : "+f"(c[0]), "+f"(c[1]), "+f"(c[2]), "+f"(c[3])
        : "r"(a[0]), "r"(a[1]), "r"(a[2]), "r"(a[3]),
          "r"(b[0]), "r"(b[1]));
}

__device__ __forceinline__ u32 prmt(u32 a, u32 b, u32 sel) {
    u32 r; asm("prmt.b32 %0, %1, %2, %3;" : "=r"(r) : "r"(a), "r"(b), "r"(sel));
    return r;
}

// ======================= GEMM: C = A @ W + bias =============================
// 128x128 block tile, ktile 32, 8 warps (2m x 4n), double-buffered smem.
// PRE:  A comes pre-split (u32 hi/lo arrays)  SOUT: write split u32 output.

#define AS 20     // A smem row stride (16 kpairs + 4 pad) in u32
#define BS 136    // B smem row stride (128 n + 8 pad) in u32
#define STG (128 * AS * 2 + 16 * BS * 2)   // 9472 u32 per stage
#define GEMM_SMEM (2 * STG * 4)            // 75776 B
#define NK  (D_MODEL / 32)

template<bool PRE, bool SOUT>
__device__ __forceinline__ void gemm_body(
    const float* __restrict__ A,
    const u32* __restrict__ Agh, const u32* __restrict__ Agl,
    const float* __restrict__ W, const float* __restrict__ bias,
    float* __restrict__ C, u32* __restrict__ Cgh, u32* __restrict__ Cgl,
    u32* sm)
{
    const int tid  = threadIdx.x;
    const int warp = tid >> 5;
    const int lane = tid & 31;
    const int g    = lane >> 2;
    const int tg   = lane & 3;
    const int wm   = warp >> 2;
    const int wn   = warp & 3;
    const int brow = blockIdx.y;
    const int bcol = blockIdx.x;

    float c[4][4][4];
    #pragma unroll
    for (int mf = 0; mf < 4; mf++)
        #pragma unroll
        for (int nf = 0; nf < 4; nf++)
            #pragma unroll
            for (int i = 0; i < 4; i++) c[mf][nf][i] = 0.0f;

    const int arow  = tid >> 3;          // 0..31 (+32i)
    const int acol  = (tid & 7) << 2;    // fp32 cols 0..28
    const int ac2   = (tid & 7) << 1;    // u32 pair cols 0..14
    const int bln   = lane & 15;
    const int bhalf = lane >> 4;

    const float* Ag  = A   + (size_t)(brow * 128) * D_MODEL;
    const u32*   Agh0 = Agh + (size_t)(brow * 128) * U;
    const u32*   Agl0 = Agl + (size_t)(brow * 128) * U;
    const float* Wg  = W + bcol * 128;

    float4 av[4];               // PRE=false
    uint2  ah2[4], al2[4];      // PRE=true
    float4 bv[2][2];

#define G_LOAD(K0) do {                                                        \
    if (PRE) {                                                                 \
        _Pragma("unroll")                                                      \
        for (int i = 0; i < 4; i++) {                                          \
            size_t off = (size_t)(i * 32 + arow) * U + ((K0) >> 1) + ac2;      \
            ah2[i] = *(const uint2*)&Agh0[off];                                \
            al2[i] = *(const uint2*)&Agl0[off];                                \
        }                                                                      \
    } else {                                                                   \
        _Pragma("unroll")                                                      \
        for (int i = 0; i < 4; i++)                                            \
            av[i] = *(const float4*)(Ag + (size_t)(i * 32 + arow) * D_MODEL    \
                                     + (K0) + acol);                           \
    }                                                                          \
    _Pragma("unroll")                                                          \
    for (int i = 0; i < 2; i++) {                                              \
        int krow = (K0) + 2 * (warp + 8 * i) + bhalf;                          \
        _Pragma("unroll")                                                      \
        for (int j = 0; j < 2; j++)                                            \
            bv[i][j] = *(const float4*)(Wg + (size_t)krow * D_MODEL            \
                                        + 4 * bln + 64 * j);                   \
    }                                                                          \
} while (0)

#define G_STORE(S) do {                                                        \
    u32* Ah_ = sm + (S) * STG;                                                 \
    u32* Al_ = Ah_ + 2560;                                                     \
    u32* Bh_ = Ah_ + 5120;                                                     \
    u32* Bl_ = Ah_ + 7296;                                                     \
    if (PRE) {                                                                 \
        _Pragma("unroll")                                                      \
        for (int i = 0; i < 4; i++) {                                          \
            int r = i * 32 + arow;                                             \
            *(uint2*)&Ah_[r * AS + ac2] = ah2[i];                              \
            *(uint2*)&Al_[r * AS + ac2] = al2[i];                              \
        }                                                                      \
    } else {                                                                   \
        _Pragma("unroll")                                                      \
        for (int i = 0; i < 4; i++) {                                          \
            int r = i * 32 + arow;                                             \
            u32 h0, l0, h1, l1;                                                \
            split2(av[i].x, av[i].y, h0, l0);                                  \
            split2(av[i].z, av[i].w, h1, l1);                                  \
            *(uint2*)&Ah_[r * AS + ac2] = make_uint2(h0, h1);                  \
            *(uint2*)&Al_[r * AS + ac2] = make_uint2(l0, l1);                  \
        }                                                                      \
    }                                                                          \
    _Pragma("unroll")                                                          \
    for (int i = 0; i < 2; i++) {                                              \
        int kp = warp + 8 * i;                                                 \
        _Pragma("unroll")                                                      \
        for (int j = 0; j < 2; j++) {                                          \
            u32 h2a, l2a, h2b, l2b;                                            \
            split2(bv[i][j].x, bv[i][j].y, h2a, l2a);                          \
            split2(bv[i][j].z, bv[i][j].w, h2b, l2b);                          \
            u32 ph2a = __shfl_xor_sync(0xffffffffu, h2a, 16);                  \
            u32 ph2b = __shfl_xor_sync(0xffffffffu, h2b, 16);                  \
            u32 pl2a = __shfl_xor_sync(0xffffffffu, l2a, 16);                  \
            u32 pl2b = __shfl_xor_sync(0xffffffffu, l2b, 16);                  \
            int col = 4 * bln + 64 * j;                                        \
            if (bhalf == 0) {                                                  \
                uint4 o = make_uint4(prmt(h2a, ph2a, 0x5410),                  \
                                     prmt(h2a, ph2a, 0x7632),                  \
                                     prmt(h2b, ph2b, 0x5410),                  \
                                     prmt(h2b, ph2b, 0x7632));                 \
                *(uint4*)&Bh_[kp * BS + col] = o;                              \
            } else {                                                           \
                uint4 o = make_uint4(prmt(pl2a, l2a, 0x5410),                  \
                                     prmt(pl2a, l2a, 0x7632),                  \
                                     prmt(pl2b, l2b, 0x5410),                  \
                                     prmt(pl2b, l2b, 0x7632));                 \
                *(uint4*)&Bl_[kp * BS + col] = o;                              \
            }                                                                  \
        }                                                                      \
    }                                                                          \
} while (0)

    G_LOAD(0);
    G_STORE(0);
    __syncthreads();

    #pragma unroll 1
    for (int kt = 0; kt < NK; kt++) {
        const int cur = kt & 1;
        if (kt + 1 < NK) G_LOAD((kt + 1) * 32);

        const u32* Ah_ = sm + cur * STG;
        const u32* Al_ = Ah_ + 2560;
        const u32* Bh_ = Ah_ + 5120;
        const u32* Bl_ = Ah_ + 7296;

        #pragma unroll
        for (int ks = 0; ks < 2; ks++) {
            u32 ah[4][4], al[4][4];
            #pragma unroll
            for (int mf = 0; mf < 4; mf++) {
                int r0 = (wm * 64 + mf * 16 + g) * AS;
                int r1 = r0 + 8 * AS;
                int kb = 8 * ks + tg;
                ah[mf][0] = Ah_[r0 + kb];     ah[mf][1] = Ah_[r1 + kb];
                ah[mf][2] = Ah_[r0 + kb + 4]; ah[mf][3] = Ah_[r1 + kb + 4];
                al[mf][0] = Al_[r0 + kb];     al[mf][1] = Al_[r1 + kb];
                al[mf][2] = Al_[r0 + kb + 4]; al[mf][3] = Al_[r1 + kb + 4];
            }
            u32 bh[4][2], bl[4][2];
            #pragma unroll
            for (int nf = 0; nf < 4; nf++) {
                int cn = wn * 32 + nf * 8 + g;
                bh[nf][0] = Bh_[(8 * ks + tg) * BS + cn];
                bh[nf][1] = Bh_[(8 * ks + tg + 4) * BS + cn];
                bl[nf][0] = Bl_[(8 * ks + tg) * BS + cn];
                bl[nf][1] = Bl_[(8 * ks + tg + 4) * BS + cn];
            }
            #pragma unroll
            for (int mf = 0; mf < 4; mf++)
                #pragma unroll
                for (int nf = 0; nf < 4; nf++) {
                    mma16(c[mf][nf], ah[mf], bh[nf]);
                    mma16(c[mf][nf], al[mf], bh[nf]);
                    mma16(c[mf][nf], ah[mf], bl[nf]);
                }
        }

        if (kt + 1 < NK) G_STORE((kt + 1) & 1);
        __syncthreads();
    }

    #pragma unroll
    for (int mf = 0; mf < 4; mf++) {
        int row0 = brow * 128 + wm * 64 + mf * 16 + g;
        #pragma unroll
        for (int nf = 0; nf < 4; nf++) {
            int col = bcol * 128 + wn * 32 + nf * 8 + 2 * tg;
            float b0 = bias[col], b1 = bias[col + 1];
            if (SOUT) {
                u32 h, l;
                split2(c[mf][nf][0] + b0, c[mf][nf][1] + b1, h, l);
                Cgh[(size_t)row0 * U + (col >> 1)] = h;
                Cgl[(size_t)row0 * U + (col >> 1)] = l;
                split2(c[mf][nf][2] + b0, c[mf][nf][3] + b1, h, l);
                Cgh[(size_t)(row0 + 8) * U + (col >> 1)] = h;
                Cgl[(size_t)(row0 + 8) * U + (col >> 1)] = l;
            } else {
                *(float2*)(C + (size_t)row0 * D_MODEL + col) =
                    make_float2(c[mf][nf][0] + b0, c[mf][nf][1] + b1);
                *(float2*)(C + (size_t)(row0 + 8) * D_MODEL + col) =
                    make_float2(c[mf][nf][2] + b0, c[mf][nf][3] + b1);
            }
        }
    }
#undef G_LOAD
#undef G_STORE
}

__global__ __launch_bounds__(256)
void qkv_kernel(const float* __restrict__ X,
                const float* __restrict__ wq, const float* __restrict__ bq,
                const float* __restrict__ wk, const float* __restrict__ bk,
                const float* __restrict__ wv, const float* __restrict__ bv)
{
    extern __shared__ u32 sm[];
    const float* W; const float* bias; u32 *Ch, *Cl;
    if (blockIdx.z == 0)      { W = wq; bias = bq; Ch = g_qh; Cl = g_ql; }
    else if (blockIdx.z == 1) { W = wk; bias = bk; Ch = g_kh; Cl = g_kl; }
    else                      { W = wv; bias = bv; Ch = g_vh; Cl = g_vl; }
    gemm_body<false, true>(X, nullptr, nullptr, W, bias,
                           nullptr, Ch, Cl, sm);
}

__global__ __launch_bounds__(256)
void out_proj_kernel(const float* __restrict__ wo,
                     const float* __restrict__ bo,
                     float* __restrict__ out)
{
    extern __shared__ u32 sm[];
    gemm_body<true, false>(nullptr, g_ah, g_al, wo, bo,
                           out, nullptr, nullptr, sm);
}

// ============================ Flash attention ===============================
// 128 q rows / block, 64 kv per tile, 8 warps, double-buffered K/V smem.
// All inputs pre-split; K tiles are raw u32 copies; V kv-paired via shfl+prmt.
// 1/sqrt(64) applied as exact fp32 multiply on S before softmax.

#define KSS 36
#define VSS 72
#define FSTG (64 * KSS * 2 + 32 * VSS * 2)   // 9216 u32 per stage
#define FLASH_SMEM (2 * FSTG * 4)            // 73728 B
#define NT  (SEQ / 64)

__global__ __launch_bounds__(256)
void flash_kernel()
{
    extern __shared__ u32 fsm[];

    const int tid   = threadIdx.x;
    const int warp  = tid >> 5;
    const int lane  = tid & 31;
    const int g     = lane >> 2;
    const int tg    = lane & 3;
    const int wbase = warp * 16;
    const int qt    = blockIdx.x;      // 0..15
    const int bh_   = blockIdx.y;      // 0..31
    const int b     = bh_ >> 4;
    const int h     = bh_ & 15;

    const size_t base = (size_t)b * SEQ * U + (size_t)h * (DEPTH / 2);

    // ---- Q fragments: direct u32 loads from pre-split global ----
    u32 qh[4][4], ql[4][4];
    #pragma unroll
    for (int ks = 0; ks < 4; ks++)
        #pragma unroll
        for (int p = 0; p < 4; p++) {
            int rr = qt * 128 + wbase + g + (p & 1) * 8;
            int cc = 8 * ks + tg + 4 * (p >> 1);
            qh[ks][p] = g_qh[base + (size_t)rr * U + cc];
            ql[ks][p] = g_ql[base + (size_t)rr * U + cc];
        }

    float o[8][4];
    #pragma unroll
    for (int nf = 0; nf < 8; nf++)
        #pragma unroll
        for (int i = 0; i < 4; i++) o[nf][i] = 0.0f;
    float m0 = -1e30f, m1 = -1e30f, l0 = 0.0f, l1 = 0.0f;

    uint4 kh4[2], kl4[2];
    uint2 vh2[4], vl2[4];

#define F_LOAD(KT) do {                                                        \
    _Pragma("unroll")                                                          \
    for (int i = 0; i < 2; i++) {                                              \
        int idx = i * 256 + tid;                                               \
        int r   = idx >> 3;                                                    \
        int c4  = (idx & 7) << 2;                                              \
        size_t off = base + (size_t)((KT) * 64 + r) * U + c4;                  \
        kh4[i] = *(const uint4*)&g_kh[off];                                    \
        kl4[i] = *(const uint4*)&g_kl[off];                                    \
    }                                                                          \
    _Pragma("unroll")                                                          \
    for (int i = 0; i < 4; i++) {                                              \
        int idx = i * 256 + tid;                                               \
        int r   = idx >> 4;                                                    \
        int c2  = (idx & 15) << 1;                                             \
        size_t off = base + (size_t)((KT) * 64 + r) * U + c2;                  \
        vh2[i] = *(const uint2*)&g_vh[off];                                    \
        vl2[i] = *(const uint2*)&g_vl[off];                                    \
    }                                                                          \
} while (0)

#define F_STORE(S) do {                                                        \
    u32* Kh_ = fsm + (S) * FSTG;                                               \
    u32* Kl_ = Kh_ + 2304;                                                     \
    u32* Vh_ = Kh_ + 4608;                                                     \
    u32* Vl_ = Kh_ + 6912;                                                     \
    _Pragma("unroll")                                                          \
    for (int i = 0; i < 2; i++) {                                              \
        int idx = i * 256 + tid;                                               \
        int r   = idx >> 3;                                                    \
        int c4  = (idx & 7) << 2;                                              \
        *(uint4*)&Kh_[r * KSS + c4] = kh4[i];                                  \
        *(uint4*)&Kl_[r * KSS + c4] = kl4[i];                                  \
    }                                                                          \
    _Pragma("unroll")                                                          \
    for (int i = 0; i < 4; i++) {                                              \
        int idx = i * 256 + tid;                                               \
        int rp  = idx >> 5;                                                    \
        int c2  = (idx & 15) << 1;                                             \
        u32 xh0 = vh2[i].x, xh1 = vh2[i].y;                                    \
        u32 xl0 = vl2[i].x, xl1 = vl2[i].y;                                    \
        u32 yh0 = __shfl_xor_sync(0xffffffffu, xh0, 16);                       \
        u32 yh1 = __shfl_xor_sync(0xffffffffu, xh1, 16);                       \
        u32 yl0 = __shfl_xor_sync(0xffffffffu, xl0, 16);                       \
        u32 yl1 = __shfl_xor_sync(0xffffffffu, xl1, 16);                       \
        if (lane < 16) {                                                       \
            uint4 ov = make_uint4(prmt(xh0, yh0, 0x5410),                      \
                                  prmt(xh0, yh0, 0x7632),                      \
                                  prmt(xh1, yh1, 0x5410),                      \
                                  prmt(xh1, yh1, 0x7632));                     \
            *(uint4*)&Vh_[rp * VSS + 2 * c2] = ov;                             \
        } else {                                                               \
            uint4 ov = make_uint4(prmt(yl0, xl0, 0x5410),                      \
                                  prmt(yl0, xl0, 0x7632),                      \
                                  prmt(yl1, xl1, 0x5410),                      \
                                  prmt(yl1, xl1, 0x7632));                     \
            *(uint4*)&Vl_[rp * VSS + 2 * c2] = ov;                             \
        }                                                                      \
    }                                                                          \
} while (0)

    F_LOAD(0);
    F_STORE(0);
    __syncthreads();

    #pragma unroll 1
    for (int kt = 0; kt < NT; kt++) {
        const int cur = kt & 1;
        if (kt + 1 < NT) F_LOAD(kt + 1);

        const u32* Kh_ = fsm + cur * FSTG;
        const u32* Kl_ = Kh_ + 2304;
        const u32* Vh_ = Kh_ + 4608;
        const u32* Vl_ = Kh_ + 6912;

        // ---- S = Q @ K^T ----
        float s[8][4];
        #pragma unroll
        for (int nf = 0; nf < 8; nf++)
            #pragma unroll
            for (int i = 0; i < 4; i++) s[nf][i] = 0.0f;

        #pragma unroll
        for (int ks = 0; ks < 4; ks++)
            #pragma unroll
            for (int nf = 0; nf < 8; nf++) {
                int j = nf * 8 + g;
                u32 kh2[2], kl2[2];
                kh2[0] = Kh_[j * KSS + 8 * ks + tg];
                kh2[1] = Kh_[j * KSS + 8 * ks + tg + 4];
                kl2[0] = Kl_[j * KSS + 8 * ks + tg];
                kl2[1] = Kl_[j * KSS + 8 * ks + tg + 4];
                mma16(s[nf], qh[ks], kh2);
                mma16(s[nf], ql[ks], kh2);
                mma16(s[nf], qh[ks], kl2);
            }

        // ---- scale (exact) + online softmax (rows g, g+8) ----
        #pragma unroll
        for (int nf = 0; nf < 8; nf++)
            #pragma unroll
            for (int i = 0; i < 4; i++) s[nf][i] *= 0.125f;

        float mx0 = -1e30f, mx1 = -1e30f;
        #pragma unroll
        for (int nf = 0; nf < 8; nf++) {
            mx0 = fmaxf(mx0, fmaxf(s[nf][0], s[nf][1]));
            mx1 = fmaxf(mx1, fmaxf(s[nf][2], s[nf][3]));
        }
        mx0 = fmaxf(mx0, __shfl_xor_sync(0xffffffffu, mx0, 1));
        mx0 = fmaxf(mx0, __shfl_xor_sync(0xffffffffu, mx0, 2));
        mx1 = fmaxf(mx1, __shfl_xor_sync(0xffffffffu, mx1, 1));
        mx1 = fmaxf(mx1, __shfl_xor_sync(0xffffffffu, mx1, 2));

        float mn0 = fmaxf(m0, mx0), mn1 = fmaxf(m1, mx1);
        float a0 = __expf(m0 - mn0), a1 = __expf(m1 - mn1);
        m0 = mn0; m1 = mn1;

        float sum0 = 0.0f, sum1 = 0.0f;
        #pragma unroll
        for (int nf = 0; nf < 8; nf++) {
            s[nf][0] = __expf(s[nf][0] - mn0); sum0 += s[nf][0];
            s[nf][1] = __expf(s[nf][1] - mn0); sum0 += s[nf][1];
            s[nf][2] = __expf(s[nf][2] - mn1); sum1 += s[nf][2];
            s[nf][3] = __expf(s[nf][3] - mn1); sum1 += s[nf][3];
        }
        sum0 += __shfl_xor_sync(0xffffffffu, sum0, 1);
        sum0 += __shfl_xor_sync(0xffffffffu, sum0, 2);
        sum1 += __shfl_xor_sync(0xffffffffu, sum1, 1);
        sum1 += __shfl_xor_sync(0xffffffffu, sum1, 2);
        l0 = l0 * a0 + sum0;
        l1 = l1 * a1 + sum1;

        #pragma unroll
        for (int nf = 0; nf < 8; nf++) {
            o[nf][0] *= a0; o[nf][1] *= a0;
            o[nf][2] *= a1; o[nf][3] *= a1;
        }

        // ---- PV: P fragments built in registers ----
        #pragma unroll
        for (int ks = 0; ks < 4; ks++) {
            u32 ph[4], pl[4];
            split2(s[2 * ks][0],     s[2 * ks][1],     ph[0], pl[0]);
            split2(s[2 * ks][2],     s[2 * ks][3],     ph[1], pl[1]);
            split2(s[2 * ks + 1][0], s[2 * ks + 1][1], ph[2], pl[2]);
            split2(s[2 * ks + 1][2], s[2 * ks + 1][3], ph[3], pl[3]);
            #pragma unroll
            for (int nf = 0; nf < 8; nf++) {
                int d = nf * 8 + g;
                u32 vh[2], vl[2];
                vh[0] = Vh_[(8 * ks + tg) * VSS + d];
                vh[1] = Vh_[(8 * ks + tg + 4) * VSS + d];
                vl[0] = Vl_[(8 * ks + tg) * VSS + d];
                vl[1] = Vl_[(8 * ks + tg + 4) * VSS + d];
                mma16(o[nf], ph, vh);
                mma16(o[nf], pl, vh);
                mma16(o[nf], ph, vl);
            }
        }

        if (kt + 1 < NT) F_STORE((kt + 1) & 1);
        __syncthreads();
    }

    // ---- normalize + split-store to g_ah/g_al ----
    float inv0 = 1.0f / l0, inv1 = 1.0f / l1;
    int row0 = qt * 128 + wbase + g;
    #pragma unroll
    for (int nf = 0; nf < 8; nf++) {
        int cc = nf * 4 + tg;          // u32 col within head
        u32 hh, ll;
        split2(o[nf][0] * inv0, o[nf][1] * inv0, hh, ll);
        g_ah[base + (size_t)row0 * U + cc] = hh;
        g_al[base + (size_t)row0 * U + cc] = ll;
        split2(o[nf][2] * inv1, o[nf][3] * inv1, hh, ll);
        g_ah[base + (size_t)(row0 + 8) * U + cc] = hh;
        g_al[base + (size_t)(row0 + 8) * U + cc] = ll;
    }
#undef F_LOAD
#undef F_STORE
}

// ============================== launch ======================================

extern "C" void kernel_launch(void* const* d_in, const int* in_sizes, int n_in,
                              void* d_out, int out_size)
{
    const float* X  = (const float*)d_in[0];
    const float* wq = (const float*)d_in[1];
    const float* bq = (const float*)d_in[2];
    const float* wk = (const float*)d_in[3];
    const float* bk = (const float*)d_in[4];
    const float* wv = (const float*)d_in[5];
    const float* bv = (const float*)d_in[6];
    const float* wo = (const float*)d_in[7];
    const float* bo = (const float*)d_in[8];
    float* out = (float*)d_out;
    (void)in_sizes; (void)n_in; (void)out_size;

    cudaFuncSetAttribute(qkv_kernel,
                         cudaFuncAttributeMaxDynamicSharedMemorySize, GEMM_SMEM);
    cudaFuncSetAttribute(out_proj_kernel,
                         cudaFuncAttributeMaxDynamicSharedMemorySize, GEMM_SMEM);
    cudaFuncSetAttribute(flash_kernel,
                         cudaFuncAttributeMaxDynamicSharedMemorySize, FLASH_SMEM);

    dim3 gproj(D_MODEL / 128, M_TOK / 128, 3);   // 8 x 32 x 3
    qkv_kernel<<<gproj, 256, GEMM_SMEM>>>(X, wq, bq, wk, bk, wv, bv);

    dim3 gflash(SEQ / 128, BATCH * NUM_HEADS);   // 16 x 32
    flash_kernel<<<gflash, 256, FLASH_SMEM>>>();

    dim3 gout(D_MODEL / 128, M_TOK / 128);       // 8 x 32
    out_proj_kernel<<<gout, 256, GEMM_SMEM>>>(wo, bo, out);
}